// round 16
// baseline (speedup 1.0000x reference)
#include <cuda_runtime.h>

#define E     1024
#define LAY   24
#define HID   4096
#define VOCAB 50277
#define NBLK  128
#define NTHR  512
#define NWARP 16
#define GW_H  (NBLK * NWARP)   // 2048 head warps
#define SL    8                // E-slice per block  (128*8  = 1024)
#define HSL   32               // HID-slice per block (128*32 = 4096)

// ---------------- scratch (device globals; re-initialized every call) -------
__device__ __align__(16) float g_bufA[E];
__device__ __align__(16) float g_bufB[E];
__device__ __align__(16) float g_ffn[2][E];
__device__ __align__(16) float g_rf[E];
__device__ unsigned g_bar_leaf[8];
__device__ unsigned g_bar_root;
__device__ volatile unsigned g_bar_gen;

struct Params {
    const int*   ctx;
    const float *xx_att, *aa_att, *bb_att, *pp_att, *xx_ffn;
    const float *emb_w, *head_w;
    const float *ln0_w, *ln0_b, *ln1_w, *ln1_b, *ln2_w, *ln2_b, *lno_w, *lno_b;
    const float *mk, *mv, *mr, *tf, *td;
    const float *Wr, *Wk, *Wv, *Wo;
    const float *fmk, *fmr, *Fr, *Fk, *Fv;
    float* out;
};

// ------------- two-level software grid barrier (proven) ---------------------
__device__ __forceinline__ void grid_sync() {
    __syncthreads();
    if (threadIdx.x == 0) {
        const unsigned gen = g_bar_gen;
        const int b = blockIdx.x & 7;            // 128 = 8 buckets x 16
        __threadfence();
        if (atomicAdd(&g_bar_leaf[b], 1u) == 15u) {
            atomicExch(&g_bar_leaf[b], 0u);
            if (atomicAdd(&g_bar_root, 1u) == 7u) {
                atomicExch(&g_bar_root, 0u);
                __threadfence();
                g_bar_gen = gen + 1u;
            } else {
                while (g_bar_gen == gen) { __nanosleep(32); }
            }
        } else {
            while (g_bar_gen == gen) { __nanosleep(32); }
        }
        __threadfence();
    }
    __syncthreads();
}

// ---------------- block reduction ------------------------------------------
__device__ __forceinline__ float block_sum(float v, float* red) {
    #pragma unroll
    for (int o = 16; o; o >>= 1) v += __shfl_xor_sync(0xffffffffu, v, o);
    int w = threadIdx.x >> 5;
    if ((threadIdx.x & 31) == 0) red[w] = v;
    __syncthreads();
    if (threadIdx.x < 32) {
        float t = (threadIdx.x < NWARP) ? red[threadIdx.x] : 0.f;
        #pragma unroll
        for (int o = 16; o; o >>= 1) t += __shfl_xor_sync(0xffffffffu, t, o);
        if (threadIdx.x == 0) red[0] = t;
    }
    __syncthreads();
    float r = red[0];
    __syncthreads();
    return r;
}

// ---------------- GEMV pieces ------------------------------------------------
__device__ __forceinline__ float red32(float s) {
    #pragma unroll
    for (int o = 16; o; o >>= 1) s += __shfl_xor_sync(0xffffffffu, s, o);
    return s;
}

__device__ __forceinline__ void pf8(const float* __restrict__ Wrow, int lane,
                                    float4 (&a)[8]) {
    const float4* W = (const float4*)Wrow;
    #pragma unroll
    for (int t = 0; t < 8; t++) a[t] = W[lane + 32 * t];
}

__device__ __forceinline__ float dot8_pf(const float4 (&a)[8],
                                         const float* __restrict__ vec, int lane) {
    const float4* v = (const float4*)vec;
    float s = 0.f;
    #pragma unroll
    for (int t = 0; t < 8; t++) {
        float4 x = v[lane + 32 * t];
        s = fmaf(a[t].x, x.x, s); s = fmaf(a[t].y, x.y, s);
        s = fmaf(a[t].z, x.z, s); s = fmaf(a[t].w, x.w, s);
    }
    return red32(s);
}

__device__ __forceinline__ float sigmoidf_(float x) {
    return 1.f / (1.f + expf(-x));
}

// ---------------- the whole network: 2 grid barriers per layer --------------
__global__ void __launch_bounds__(NTHR, 1) rwkv_kernel(Params p) {
    __shared__ __align__(16) float sh0[E];
    __shared__ __align__(16) float sh1[E];
    __shared__ __align__(16) float sh2[E];
    __shared__ float red[NWARP];
    __shared__ float st_A[SL], st_B[SL], st_X[SL];
    __shared__ __align__(16) float s_r[SL], s_k[SL], s_v[SL], s_oin[SL];
    __shared__ __align__(16) float s_kf[HSL];

    const int tid  = threadIdx.x;
    const int wid  = tid >> 5;
    const int lane = tid & 31;
    const int b    = blockIdx.x;
    const int j0 = tid, j1 = tid + NTHR;
    const int i_lo = b * SL;          // E-slice base
    const int h_lo = b * HSL;         // HID-slice base
    const int ghw  = b * NWARP + wid; // head warp id

    float* outv  = p.out;
    float* o_xx  = p.out + VOCAB;
    float* o_aa  = o_xx  + LAY * E;
    float* o_bb  = o_aa  + LAY * E;
    float* o_pp  = o_bb  + LAY * E;
    float* o_xxf = o_pp  + LAY * E;
    float* o_da  = o_xxf + LAY * E;
    float* o_db  = o_da  + LAY * E;

    float4 a[8], bb4[8];              // cross-barrier row buffers
    float4 wo0[4], wo1[4];            // Wo column cache (threads 256..511)
    // cached per-layer params
    float c_sx0, c_sx1, c_mk0, c_mk1, c_mv0, c_mv1, c_mr0, c_mr1;  // AB mixes
    float c_xf0, c_xf1, c_fk0, c_fk1, c_fr0, c_fr1;                // CD mixes
    float w_aa, w_bb, w_pp, w_tf, w_td;                            // WKV (tid<8)

    // ---------------- init: x0 = LN(emb[tok], ln0); seed + RESET state ------
    {
        int tok = p.ctx[0];
        const float* er = p.emb_w + (size_t)tok * E;
        float e0 = er[j0], e1 = er[j1];
        float mean = block_sum(e0 + e1, red) * (1.f / E);
        float d0 = e0 - mean, d1 = e1 - mean;
        float inv = rsqrtf(block_sum(d0 * d0 + d1 * d1, red) * (1.f / E) + 1e-5f);
        float x00 = d0 * inv * p.ln0_w[j0] + p.ln0_b[j0];
        float x01 = d1 * inv * p.ln0_w[j1] + p.ln0_b[j1];
        if ((j0 >> 3) == b) { g_bufA[j0] = x00; g_bufB[j0] = x00; st_B[j0 & 7] = x00; }
        if ((j1 >> 3) == b) { g_bufA[j1] = x01; g_bufB[j1] = x01; st_B[j1 & 7] = x01; }
        // CRITICAL: reset cross-call state (graph replay reuses device globals)
        if (tid < SL) {
            int i = i_lo + tid;
            g_ffn[0][i] = 0.f;
            g_ffn[1][i] = 0.f;
            g_rf[i]     = 0.f;
        }
    }
    // preload AB(0) weights + params
    if (wid < 8) {
        pf8(p.Wr + (size_t)(i_lo + wid) * E, lane, a);
        pf8(p.Wv + (size_t)(i_lo + wid) * E, lane, bb4);
    } else {
        pf8(p.Wk + (size_t)(i_lo + wid - 8) * E, lane, a);
    }
    if (tid >= 256) {
        #pragma unroll
        for (int c = 0; c < 4; c++) {
            const float* q = p.Wo + (size_t)((tid - 256) + 256 * c) * E + i_lo;
            wo0[c] = *(const float4*)q;
            wo1[c] = *(const float4*)(q + 4);
        }
    }
    c_sx0 = p.xx_att[j0]; c_sx1 = p.xx_att[j1];
    c_mk0 = p.mk[j0]; c_mk1 = p.mk[j1];
    c_mv0 = p.mv[j0]; c_mv1 = p.mv[j1];
    c_mr0 = p.mr[j0]; c_mr1 = p.mr[j1];
    if (tid < SL) {
        int i = i_lo + tid;
        w_aa = p.aa_att[i]; w_bb = p.bb_att[i]; w_pp = p.pp_att[i];
        w_tf = p.tf[i];     w_td = p.td[i];
    }
    grid_sync();

    for (int l = 0; l < LAY; l++) {
        const size_t lE  = (size_t)l * E;
        const size_t lEE = (size_t)l * E * E;
        const size_t lHE = (size_t)l * HID * E;
        const size_t lEH = (size_t)l * E * HID;
        const int par_r = (l + 1) & 1;   // ffn parity read at AB / zeroed at CD
        const int par_w = l & 1;         // ffn parity written at CD

        // ========== Phase AB: LN1 + mixes + r/k/v + WKV + Wo partials ======
        {
            float xa0 = g_bufA[j0], xa1 = g_bufA[j1];
            float xc0 = xa0 + g_rf[j0] * g_ffn[par_r][j0];
            float xc1 = xa1 + g_rf[j1] * g_ffn[par_r][j1];
            float mean = block_sum(xc0 + xc1, red) * (1.f / E);
            float d0 = xc0 - mean, d1 = xc1 - mean;
            float inv = rsqrtf(block_sum(d0 * d0 + d1 * d1, red) * (1.f / E) + 1e-5f);
            float xn0 = d0 * inv * p.ln1_w[lE + j0] + p.ln1_b[lE + j0];
            float xn1 = d1 * inv * p.ln1_w[lE + j1] + p.ln1_b[lE + j1];
            if ((j0 >> 3) == b) { st_A[j0 & 7] = xa0; st_X[j0 & 7] = xc0; o_xx[lE + j0] = xn0; }
            if ((j1 >> 3) == b) { st_A[j1 & 7] = xa1; st_X[j1 & 7] = xc1; o_xx[lE + j1] = xn1; }
            sh0[j0] = xn0 * c_mk0 + c_sx0 * (1.f - c_mk0);   // xk
            sh0[j1] = xn1 * c_mk1 + c_sx1 * (1.f - c_mk1);
            sh1[j0] = xn0 * c_mv0 + c_sx0 * (1.f - c_mv0);   // xv
            sh1[j1] = xn1 * c_mv1 + c_sx1 * (1.f - c_mv1);
            sh2[j0] = xn0 * c_mr0 + c_sx0 * (1.f - c_mr0);   // xr
            sh2[j1] = xn1 * c_mr1 + c_sx1 * (1.f - c_mr1);
            __syncthreads();
            if (wid < 8) {
                float s = dot8_pf(a, sh2, lane);             // r row
                if (lane == 0) s_r[wid] = s;
                s = dot8_pf(bb4, sh1, lane);                 // v row
                if (lane == 0) s_v[wid] = s;
            } else {
                float s = dot8_pf(a, sh0, lane);             // k row
                if (lane == 0) s_k[wid - 8] = s;
            }
            __syncthreads();
            if (tid < SL) {
                int i = i_lo + tid;
                float kj = s_k[tid], vj = s_v[tid], rp = s_r[tid];
                float ww = w_tf + kj;
                float q  = fmaxf(w_pp, ww);
                float e1 = expf(w_pp - q), e2 = expf(ww - q);
                float rr = sigmoidf_(rp);
                s_oin[tid] = rr * (e1 * w_aa + e2 * vj) / (e1 * w_bb + e2);
                float ww2 = w_pp + w_td;
                float q2  = fmaxf(ww2, kj);
                float f1  = expf(ww2 - q2), f2 = expf(kj - q2);
                o_aa[lE + i] = f1 * w_aa + f2 * vj;
                o_bb[lE + i] = f1 * w_bb + f2;
                o_pp[lE + i] = q2;
                o_da[lE + i] = rp;
                o_db[lE + i] = rr;
                atomicAdd(&g_bufB[i], st_X[tid] - st_B[tid]);   // owner delta
            }
            __syncthreads();
            if (tid >= 256) {
                float4 o0 = *(const float4*)&s_oin[0];
                float4 o1 = *(const float4*)&s_oin[4];
                #pragma unroll
                for (int c = 0; c < 4; c++) {
                    int row = (tid - 256) + 256 * c;
                    float s = wo0[c].x * o0.x + wo0[c].y * o0.y
                            + wo0[c].z * o0.z + wo0[c].w * o0.w
                            + wo1[c].x * o1.x + wo1[c].y * o1.y
                            + wo1[c].z * o1.z + wo1[c].w * o1.w;
                    atomicAdd(&g_bufB[row], s);
                }
            }
            // preload CD rows (Fk) + CD params
            pf8(p.Fk + lHE + (size_t)(h_lo + 2 * wid) * E, lane, a);
            pf8(p.Fk + lHE + (size_t)(h_lo + 2 * wid + 1) * E, lane, bb4);
            c_xf0 = p.xx_ffn[lE + j0]; c_xf1 = p.xx_ffn[lE + j1];
            c_fk0 = p.fmk[lE + j0];    c_fk1 = p.fmk[lE + j1];
            c_fr0 = p.fmr[lE + j0];    c_fr1 = p.fmr[lE + j1];
        }
        grid_sync();

        // ========== Phase CD: LN2 + mixes + Fk/Fr + Fv column partials =====
        {
            float xb0 = g_bufB[j0], xb1 = g_bufB[j1];
            float mean = block_sum(xb0 + xb1, red) * (1.f / E);
            float d0 = xb0 - mean, d1 = xb1 - mean;
            float inv = rsqrtf(block_sum(d0 * d0 + d1 * d1, red) * (1.f / E) + 1e-5f);
            float xn0 = d0 * inv * p.ln2_w[lE + j0] + p.ln2_b[lE + j0];
            float xn1 = d1 * inv * p.ln2_w[lE + j1] + p.ln2_b[lE + j1];
            if ((j0 >> 3) == b) { st_B[j0 & 7] = xb0; o_xxf[lE + j0] = xn0; }
            if ((j1 >> 3) == b) { st_B[j1 & 7] = xb1; o_xxf[lE + j1] = xn1; }
            sh0[j0] = xn0 * c_fk0 + c_xf0 * (1.f - c_fk0);   // fxk
            sh0[j1] = xn1 * c_fk1 + c_xf1 * (1.f - c_fk1);
            sh1[j0] = xn0 * c_fr0 + c_xf0 * (1.f - c_fr0);   // fxr
            sh1[j1] = xn1 * c_fr1 + c_xf1 * (1.f - c_fr1);
            __syncthreads();
            if (tid < SL) {
                int i = i_lo + tid;
                atomicAdd(&g_bufA[i], st_B[tid] - st_A[tid]);   // owner delta
                g_ffn[par_r][i] = 0.f;                          // zero for CD(l+1)
            }
            {
                float s = dot8_pf(a, sh0, lane);                // Fk row 2w
                s = fmaxf(s, 0.f);
                if (lane == 0) s_kf[2 * wid] = s * s;
                if (wid < 8)                                     // reuse a for Fr
                    pf8(p.Fr + lEE + (size_t)(i_lo + wid) * E, lane, a);
                s = dot8_pf(bb4, sh0, lane);                    // Fk row 2w+1
                s = fmaxf(s, 0.f);
                if (lane == 0) s_kf[2 * wid + 1] = s * s;
                if (wid < 8) {
                    s = dot8_pf(a, sh1, lane);                  // Fr row
                    if (lane == 0) g_rf[i_lo + wid] = sigmoidf_(s);
                }
            }
            __syncthreads();
            // Fv column partials: 8 lanes per row, fully coalesced
            {
                const int sub = lane >> 3, q8 = lane & 7;
                float4 kfv = *(const float4*)&s_kf[q8 * 4];
                const float* Fvb = p.Fv + lEH + h_lo + q8 * 4;
                #pragma unroll 4
                for (int pp2 = 0; pp2 < 16; pp2++) {
                    int row = pp2 * 64 + wid * 4 + sub;
                    float4 v = *(const float4*)(Fvb + (size_t)row * HID);
                    float s = v.x * kfv.x + v.y * kfv.y + v.z * kfv.z + v.w * kfv.w;
                    s += __shfl_xor_sync(0xffffffffu, s, 1);
                    s += __shfl_xor_sync(0xffffffffu, s, 2);
                    s += __shfl_xor_sync(0xffffffffu, s, 4);
                    if (q8 == 0) atomicAdd(&g_ffn[par_w][row], s);
                }
            }
            // preload next AB / head + params
            if (l + 1 < LAY) {
                const size_t nEE = lEE + (size_t)E * E;
                const size_t nE  = lE + E;
                if (wid < 8) {
                    pf8(p.Wr + nEE + (size_t)(i_lo + wid) * E, lane, a);
                    pf8(p.Wv + nEE + (size_t)(i_lo + wid) * E, lane, bb4);
                } else {
                    pf8(p.Wk + nEE + (size_t)(i_lo + wid - 8) * E, lane, a);
                }
                if (tid >= 256) {
                    #pragma unroll
                    for (int c = 0; c < 4; c++) {
                        const float* q = p.Wo + nEE
                                       + (size_t)((tid - 256) + 256 * c) * E + i_lo;
                        wo0[c] = *(const float4*)q;
                        wo1[c] = *(const float4*)(q + 4);
                    }
                }
                c_sx0 = p.xx_att[nE + j0]; c_sx1 = p.xx_att[nE + j1];
                c_mk0 = p.mk[nE + j0]; c_mk1 = p.mk[nE + j1];
                c_mv0 = p.mv[nE + j0]; c_mv1 = p.mv[nE + j1];
                c_mr0 = p.mr[nE + j0]; c_mr1 = p.mr[nE + j1];
                if (tid < SL) {
                    int i = i_lo + tid;
                    w_aa = p.aa_att[nE + i]; w_bb = p.bb_att[nE + i];
                    w_pp = p.pp_att[nE + i];
                    w_tf = p.tf[nE + i];     w_td = p.td[nE + i];
                }
            } else {
                pf8(p.head_w + (size_t)ghw * E, lane, a);
                pf8(p.head_w + (size_t)(ghw + GW_H) * E, lane, bb4);
                c_sx0 = p.lno_w[j0]; c_sx1 = p.lno_w[j1];   // reuse: w
                c_mk0 = p.lno_b[j0]; c_mk1 = p.lno_b[j1];   // reuse: b
            }
        }
        grid_sync();
    }

    // ================= head: final LN + [V,E] GEMV (ping-pong) =============
    {
        float xf0 = g_bufA[j0] + g_rf[j0] * g_ffn[(LAY - 1) & 1][j0];
        float xf1 = g_bufA[j1] + g_rf[j1] * g_ffn[(LAY - 1) & 1][j1];
        float mean = block_sum(xf0 + xf1, red) * (1.f / E);
        float d0 = xf0 - mean, d1 = xf1 - mean;
        float inv = rsqrtf(block_sum(d0 * d0 + d1 * d1, red) * (1.f / E) + 1e-5f);
        sh0[j0] = d0 * inv * c_sx0 + c_mk0;
        sh0[j1] = d1 * inv * c_sx1 + c_mk1;
        __syncthreads();
    }
    {
        int row = ghw;
        while (true) {
            float s = dot8_pf(a, sh0, lane);
            if (lane == 0) outv[row] = s;
            int rn = row + GW_H;
            if (rn >= VOCAB) break;
            int rp2 = row + 2 * GW_H;
            if (rp2 < VOCAB) pf8(p.head_w + (size_t)rp2 * E, lane, a);
            s = dot8_pf(bb4, sh0, lane);
            if (lane == 0) outv[rn] = s;
            row = rp2;
            if (row >= VOCAB) break;
            int rq = rn + 2 * GW_H;
            if (rq < VOCAB) pf8(p.head_w + (size_t)rq * E, lane, bb4);
        }
    }
}

extern "C" void kernel_launch(void* const* d_in, const int* in_sizes, int n_in,
                              void* d_out, int out_size) {
    Params p;
    p.ctx    = (const int*)  d_in[0];
    p.xx_att = (const float*)d_in[1];
    p.aa_att = (const float*)d_in[2];
    p.bb_att = (const float*)d_in[3];
    p.pp_att = (const float*)d_in[4];
    p.xx_ffn = (const float*)d_in[5];
    p.emb_w  = (const float*)d_in[6];
    p.head_w = (const float*)d_in[7];
    p.ln0_w  = (const float*)d_in[8];
    p.ln0_b  = (const float*)d_in[9];
    p.ln1_w  = (const float*)d_in[10];
    p.ln1_b  = (const float*)d_in[11];
    p.ln2_w  = (const float*)d_in[12];
    p.ln2_b  = (const float*)d_in[13];
    p.lno_w  = (const float*)d_in[14];
    p.lno_b  = (const float*)d_in[15];
    p.mk     = (const float*)d_in[16];
    p.mv     = (const float*)d_in[17];
    p.mr     = (const float*)d_in[18];
    p.tf     = (const float*)d_in[19];
    p.td     = (const float*)d_in[20];
    p.Wr     = (const float*)d_in[21];
    p.Wk     = (const float*)d_in[22];
    p.Wv     = (const float*)d_in[23];
    p.Wo     = (const float*)d_in[24];
    p.fmk    = (const float*)d_in[25];
    p.fmr    = (const float*)d_in[26];
    p.Fr     = (const float*)d_in[27];
    p.Fk     = (const float*)d_in[28];
    p.Fv     = (const float*)d_in[29];
    p.out    = (float*)d_out;

    rwkv_kernel<<<NBLK, NTHR>>>(p);
}